// round 17
// baseline (speedup 1.0000x reference)
#include <cuda_runtime.h>
#include <cuda_bf16.h>

#define N_TRIALS   8
#define T_TOTAL    600
#define N_NEURONS  30000
#define T_USE      500
#define N_SAMPLES  50
#define MAX_COUNT  200
#define N_BINS     16
#define EPS        1e-7f
#define SYNC_COST  10.0f

#define NJ          8                  // per-sample id chunks
#define JMAX        32                 // >= ceil(MAX_COUNT/NJ) = 25
#define G_BLOCKS    (N_SAMPLES * 4 * NJ)       // 1600 gather blocks
#define TOTAL_BLOCKS (G_BLOCKS + N_SAMPLES)    // +50 fano blocks
#define BLOCKS_PER_SAMPLE 32           // 4 t-chunks x 8 j-chunks

__constant__ int c_bins[N_BINS] = {1,1,2,3,4,6,9,13,18,26,38,55,78,113,162,234};

// Scratch (device globals: allocation is forbidden).
// g_part is 16B-aligned: it is read via float4 in the fano blocks.
__device__ __align__(16) float g_part[NJ * N_SAMPLES * T_USE];
__device__ float               g_fano[N_BINS * N_SAMPLES];
__device__ unsigned int        g_scnt[N_SAMPLES];   // per-sample gather arrivals
__device__ unsigned int        g_ticket;            // fano-block ticket
// counters reset in-kernel by their consumers -> graph-replay safe

// ---------------------------------------------------------------------------
// Single fused launch, 1650 blocks x 128 threads.
// __launch_bounds__(128, 13): regs capped at 39 => >=13 blocks/SM resident
// => 148*13 = 1924 >= 1650 => ALL blocks (gather + fano) are co-resident in
// wave 1, so fano blocks may safely spin-wait: gather progress is guaranteed.
//
// Blocks [0, 1600): gather (R13 body verbatim; measured at the DRAM
//   unique-line floor). s = bid%50, tc = (bid/50)%4, jc = bid/200.
//   After writing partials: threadfence + per-sample arrival count.
// Blocks [1600, 1650): one per sample. Spin (nanosleep) until the sample's
//   32 gather blocks arrived, reset the counter, combine partials -> smem
//   (vectorized), 4 warps x 4 bins -> g_fano. Last fano block (ticket) does
//   the MSE scalar. Runs OVERLAPPED with other samples' gathers, so only the
//   last sample's fano (~2-3us) is exposed -- and the 2nd launch (+~7us of
//   overhead/gap measured across 5 fano variants) is eliminated.
//
// mask is prefix-form (arange < count) => effective count = sum(mask);
// ids[0:cnt] are exactly the active ids (duplicates preserved).
// sample_ids arrives as int32 (JAX x64-disabled demotes int64 -> int32).
// ---------------------------------------------------------------------------
__global__ void __launch_bounds__(128, 13)
fused_kernel(const float* __restrict__ spikes,
             const int*   __restrict__ trials,
             const int*   __restrict__ ids,
             const float* __restrict__ mask,
             const float* __restrict__ exp_fanos,
             float*       __restrict__ out)
{
    const int bid  = blockIdx.x;
    const int tid  = threadIdx.x;
    const int lane = tid & 31;
    const int wid  = tid >> 5;

    if (bid < G_BLOCKS) {
        // ================= gather block =================
        __shared__ int s_ids[JMAX];
        __shared__ int s_cnt;

        const int s  = bid % N_SAMPLES;
        const int tc = (bid / N_SAMPLES) % 4;
        const int jc = bid / (N_SAMPLES * 4);

        if (tid == 0) s_cnt = 0;
        __syncthreads();

        int local = 0;
        for (int j = tid; j < MAX_COUNT; j += 128)
            if (mask[s * MAX_COUNT + j] != 0.0f) local++;
        if (local) atomicAdd(&s_cnt, local);
        __syncthreads();

        const int cnt = s_cnt;
        const int lo  = (jc * cnt) / NJ;
        const int m   = ((jc + 1) * cnt) / NJ - lo;   // <= 25
        if (tid < m)
            s_ids[tid] = ids[s * MAX_COUNT + lo + tid];
        __syncthreads();

        const int t = tc * 128 + tid;
        if (t < T_USE) {
            float acc = 0.0f;
            if (m > 0) {
                const float* __restrict__ base =
                    spikes + (size_t)trials[s] * ((size_t)T_TOTAL * N_NEURONS)
                           + (size_t)t * N_NEURONS;
                int j = 0;
                for (; j + 8 <= m; j += 8) {
                    float v0 = __ldg(base + s_ids[j + 0]);
                    float v1 = __ldg(base + s_ids[j + 1]);
                    float v2 = __ldg(base + s_ids[j + 2]);
                    float v3 = __ldg(base + s_ids[j + 3]);
                    float v4 = __ldg(base + s_ids[j + 4]);
                    float v5 = __ldg(base + s_ids[j + 5]);
                    float v6 = __ldg(base + s_ids[j + 6]);
                    float v7 = __ldg(base + s_ids[j + 7]);
                    acc += ((v0 + v1) + (v2 + v3)) + ((v4 + v5) + (v6 + v7));
                }
                for (; j < m; ++j) acc += __ldg(base + s_ids[j]);
            }
            g_part[(jc * N_SAMPLES + s) * T_USE + t] = acc;
        }

        // release: partials visible before the arrival is counted
        __threadfence();
        __syncthreads();
        if (tid == 0)
            atomicAdd(&g_scnt[s], 1u);
        return;
    }

    // ================= fano block (one per sample) =================
    {
        __shared__ __align__(16) float s_row[T_USE];
        __shared__ bool s_last;

        const int s = bid - G_BLOCKS;

        if (tid == 0) {
            volatile unsigned int* cnt_ptr = (volatile unsigned int*)&g_scnt[s];
            while (*cnt_ptr < BLOCKS_PER_SAMPLE)
                __nanosleep(200);
            *cnt_ptr = 0;                           // reset for next graph replay
        }
        __syncthreads();
        __threadfence();                            // acquire: order partial reads after wait

        // combine partials -> smem row (vectorized; fixed order -> deterministic)
        // row offset (c*N_SAMPLES+s)*T_USE floats = 2000B per row -> 16B-aligned
        if (tid < T_USE / 4) {                      // 125 float4s
            float4 v = make_float4(0.0f, 0.0f, 0.0f, 0.0f);
            #pragma unroll
            for (int c = 0; c < NJ; ++c) {
                const float4 p = *(reinterpret_cast<const float4*>(
                    g_part + (size_t)(c * N_SAMPLES + s) * T_USE) + tid);
                v.x += p.x; v.y += p.y; v.z += p.z; v.w += p.w;
            }
            reinterpret_cast<float4*>(s_row)[tid] = v;
        }
        __syncthreads();

        // 4 warps x 4 bins
        #pragma unroll
        for (int rep = 0; rep < 4; ++rep) {
            const int b  = wid + rep * 4;
            const int bs = c_bins[b];
            const int nb = T_USE / bs;

            float sum = 0.0f, sumsq = 0.0f;
            for (int k = lane; k < nb; k += 32) {
                const float* rk = s_row + k * bs;
                float c = 0.0f;
                int u = 0;
                for (; u + 4 <= bs; u += 4) {
                    float a0 = rk[u], a1 = rk[u+1], a2 = rk[u+2], a3 = rk[u+3];
                    c += (a0 + a1) + (a2 + a3);
                }
                for (; u < bs; ++u) c += rk[u];
                sum   += c;
                sumsq += c * c;
            }
            #pragma unroll
            for (int off = 16; off > 0; off >>= 1) {
                sum   += __shfl_down_sync(0xffffffff, sum,   off);
                sumsq += __shfl_down_sync(0xffffffff, sumsq, off);
            }
            if (lane == 0) {
                const float mean = sum / (float)nb;
                const float var  = sumsq / (float)nb - mean * mean;
                g_fano[b * N_SAMPLES + s] = var / fmaxf(mean, EPS);
            }
        }

        // last fano block: reduce g_fano -> scalar loss
        __threadfence();
        __syncthreads();
        if (tid == 0) {
            unsigned int old = atomicAdd(&g_ticket, 1u);
            s_last = (old == N_SAMPLES - 1);
            if (s_last) g_ticket = 0;               // reset for next graph replay
        }
        __syncthreads();

        if (s_last && wid == 0) {
            float d2 = 0.0f;
            if (lane < N_BINS) {
                float fsum = 0.0f;
                for (int q = 0; q < N_SAMPLES; ++q)
                    fsum += g_fano[lane * N_SAMPLES + q];
                const float fm = fsum / (float)N_SAMPLES;
                const float d  = exp_fanos[lane] - fm;
                d2 = d * d;
            }
            #pragma unroll
            for (int off = 16; off > 0; off >>= 1)
                d2 += __shfl_down_sync(0xffffffff, d2, off);
            if (lane == 0)
                out[0] = SYNC_COST * (d2 / (float)N_BINS);
        }
    }
}

// ---------------------------------------------------------------------------
// Inputs (metadata order):
//   0: spikes float32 [8,600,30000]   1: experimental_fanos_mean float32 [16]
//   2: sample_trials int32 [50]       3: sample_ids int32 [50,200]
//   4: sample_mask float32 [50,200]   out: float32 scalar
// ---------------------------------------------------------------------------
extern "C" void kernel_launch(void* const* d_in, const int* in_sizes, int n_in,
                              void* d_out, int out_size)
{
    const float* spikes = (const float*)d_in[0];
    const float* expf_  = (const float*)d_in[1];
    const int*   trials = (const int*)d_in[2];
    const int*   ids    = (const int*)d_in[3];
    const float* mask   = (const float*)d_in[4];
    float*       out    = (float*)d_out;

    fused_kernel<<<TOTAL_BLOCKS, 128>>>(spikes, trials, ids, mask, expf_, out);
}